// round 8
// baseline (speedup 1.0000x reference)
#include <cuda_runtime.h>

// LS_loss: single fused kernel, distributed per-channel finalize.
//
// Shapes: input, img_mean : (32, 4, 512, 512) fp32, contiguous.
// 128 channels x 262144 floats (= 65536 float4 each), 16 blocks per channel.
//
// Per channel (N = 262144):
//   Hea = 0.5*(1+tanh(x/0.05))
//   A = sum(Hea), B1 = sum(Hea*img), S = sum(img), Q = sum(img^2)
//   c1 = B1/(A+eps), c2 = (S-B1)/(N-A+eps)
//   chan = Q - 2*(c1*B1 + c2*(S-B1)) + c1^2*A + c2^2*(N-A)
//   out  = sum_chan / (B*C*H*W)
//
// Arrival scheme (avoids R2's hot-counter tail):
//   - per-channel counters at 128B-strided addresses (parallel L2 slices,
//     16 arrivals each); channel's last block finalizes that channel.
//   - one 128-arrival global counter; last channel sums 128 chan values in
//     fixed index order. All reductions deterministic; counters self-reset.

#define N_PER_CH    262144
#define F4_PER_CH   65536
#define BLKS_PER_CH 16
#define NBLOCKS     (128 * BLKS_PER_CH)        // 2048
#define F4_PER_BLK  (F4_PER_CH / BLKS_PER_CH)  // 4096
#define THREADS     256
#define F4_PER_THR  (F4_PER_BLK / THREADS)     // 16
#define GRP         4
#define NGRP        (F4_PER_THR / GRP)         // 4
#define LS_EPS      1e-4f
#define INV_EPISON  20.0f
#define CTR_STRIDE  32                          // 32 uints = 128 B apart

static __device__ float4 g_partials[NBLOCKS];                 // 32 KB
static __device__ float g_chan[128];                          // per-channel loss
static __device__ unsigned int g_arrive_ch[128 * CTR_STRIDE]; // strided counters
static __device__ unsigned int g_done = 0;                    // channel-done counter

__device__ __forceinline__ float tanh_fast(float x) {
    float y;
    asm("tanh.approx.f32 %0, %1;" : "=f"(y) : "f"(x));
    return y;
}

__device__ __forceinline__ void accum1(float x, float m,
                                       float& sH, float& sHI, float& sI, float& sI2) {
    float h = fmaf(0.5f, tanh_fast(INV_EPISON * x), 0.5f);
    sH  += h;
    sHI  = fmaf(h, m, sHI);
    sI  += m;
    sI2  = fmaf(m, m, sI2);
}

__device__ __forceinline__ float4 ldcg4(const float4* p) {
    float4 v;
    asm volatile("ld.global.cg.v4.f32 {%0,%1,%2,%3}, [%4];"
                 : "=f"(v.x), "=f"(v.y), "=f"(v.z), "=f"(v.w) : "l"(p));
    return v;
}

__global__ void __launch_bounds__(THREADS, 5)
ls_loss_fused(const float4* __restrict__ inp, const float4* __restrict__ img,
              float* __restrict__ out)
{
    const int b = blockIdx.x;
    const int t = threadIdx.x;
    const int ch = b >> 4;                       // b / BLKS_PER_CH
    const long base = (long)b * F4_PER_BLK + t;

    float sH = 0.f, sHI = 0.f, sI = 0.f, sI2 = 0.f;

    #pragma unroll
    for (int g = 0; g < NGRP; g++) {
        float4 x[GRP], m[GRP];
        #pragma unroll
        for (int j = 0; j < GRP; j++) {          // front-batch 8 LDG.128
            const long idx = base + (long)(g * GRP + j) * THREADS;
            x[j] = __ldcs(&inp[idx]);
            m[j] = __ldcs(&img[idx]);
        }
        #pragma unroll
        for (int j = 0; j < GRP; j++) {
            accum1(x[j].x, m[j].x, sH, sHI, sI, sI2);
            accum1(x[j].y, m[j].y, sH, sHI, sI, sI2);
            accum1(x[j].z, m[j].z, sH, sHI, sI, sI2);
            accum1(x[j].w, m[j].w, sH, sHI, sI, sI2);
        }
    }

    // Deterministic warp tree reduce
    #pragma unroll
    for (int o = 16; o > 0; o >>= 1) {
        sH  += __shfl_down_sync(0xFFFFFFFFu, sH,  o);
        sHI += __shfl_down_sync(0xFFFFFFFFu, sHI, o);
        sI  += __shfl_down_sync(0xFFFFFFFFu, sI,  o);
        sI2 += __shfl_down_sync(0xFFFFFFFFu, sI2, o);
    }

    __shared__ float4 sm[THREADS / 32];
    __shared__ bool   s_last;
    const int warp = t >> 5, lane = t & 31;
    if (lane == 0) sm[warp] = make_float4(sH, sHI, sI, sI2);
    __syncthreads();

    if (t == 0) {
        float4 tot = sm[0];
        #pragma unroll
        for (int w = 1; w < THREADS / 32; w++) {
            float4 v = sm[w];
            tot.x += v.x; tot.y += v.y; tot.z += v.z; tot.w += v.w;
        }
        g_partials[b] = tot;
        __threadfence();                          // publish before arrive
        unsigned int prev = atomicAdd(&g_arrive_ch[ch * CTR_STRIDE], 1u);
        s_last = (prev == BLKS_PER_CH - 1);
    }
    __syncthreads();
    if (!s_last) return;

    // ---- channel finalize: last block of this channel, warp 0 only ----
    if (warp != 0) return;
    __threadfence();                              // order reads after arrivals

    float A = 0.f, B1 = 0.f, S = 0.f, Q = 0.f;
    if (lane < BLKS_PER_CH) {
        float4 v = ldcg4(&g_partials[ch * BLKS_PER_CH + lane]);
        A = v.x; B1 = v.y; S = v.z; Q = v.w;
    }
    #pragma unroll
    for (int o = 8; o > 0; o >>= 1) {             // fixed tree over 16 lanes
        A  += __shfl_down_sync(0xFFFFFFFFu, A,  o);
        B1 += __shfl_down_sync(0xFFFFFFFFu, B1, o);
        S  += __shfl_down_sync(0xFFFFFFFFu, S,  o);
        Q  += __shfl_down_sync(0xFFFFFFFFu, Q,  o);
    }

    bool last_ch = false;
    if (lane == 0) {
        const float Nf = (float)N_PER_CH;
        const float s3 = Nf - A;
        const float c1 = B1 / (A + LS_EPS);
        const float c2 = (S - B1) / (s3 + LS_EPS);
        g_chan[ch] = Q - 2.f * (c1 * B1 + c2 * (S - B1))
                   + c1 * c1 * A + c2 * c2 * s3;
        // self-reset: safe, all 16 arrivals for this channel are in
        *(volatile unsigned int*)&g_arrive_ch[ch * CTR_STRIDE] = 0u;
        __threadfence();
        unsigned int prevc = atomicAdd(&g_done, 1u);
        last_ch = (prevc == 127u);
    }
    last_ch = __shfl_sync(0xFFFFFFFFu, last_ch, 0);
    if (!last_ch) return;

    // ---- global finalize: fixed-order sum of 128 channel values ----
    __threadfence();
    if (lane == 0) {
        float tot = 0.f;
        const float4* pc = (const float4*)g_chan;
        #pragma unroll
        for (int i = 0; i < 32; i++) {            // 128 floats, fixed order
            float4 v = ldcg4(&pc[i]);
            tot += v.x; tot += v.y; tot += v.z; tot += v.w;
        }
        out[0] = tot / (float)(32 * 4 * N_PER_CH);
        *(volatile unsigned int*)&g_done = 0u;    // reset for next replay
        __threadfence();
    }
}

extern "C" void kernel_launch(void* const* d_in, const int* in_sizes, int n_in,
                              void* d_out, int out_size)
{
    const float4* inp = (const float4*)d_in[0];   // 'input'
    const float4* img = (const float4*)d_in[1];   // 'img_mean'
    ls_loss_fused<<<NBLOCKS, THREADS>>>(inp, img, (float*)d_out);
}

// round 10
// speedup vs baseline: 1.0600x; 1.0600x over previous
#include <cuda_runtime.h>

// LS_loss: two-kernel version; pass2 overlapped via PDL with an explicit
// per-block programmatic-completion trigger in pass1.
//
// Shapes: input, img_mean : (32, 4, 512, 512) fp32, contiguous.
// 128 channels x 262144 floats (= 65536 float4 each).
//
// Per channel (N = 262144):
//   Hea = 0.5*(1+tanh(x/0.05))
//   A = sum(Hea), B1 = sum(Hea*img), S = sum(img), Q = sum(img^2)
//   c1 = B1/(A+eps), c2 = (S-B1)/(N-A+eps)
//   chan = Q - 2*(c1*B1 + c2*(S-B1)) + c1^2*A + c2^2*(N-A)
//   out  = sum_chan / (B*C*H*W)
//
// pass1: 2048 blocks, 4-pair front-batched loads (MLP~8/thread); each block
//        fences its partial then fires cudaTriggerProgrammaticLaunchCompletion
//        so the dependent pass2 can ramp while pass1 drains.
// pass2: PDL launch; cudaGridDependencySynchronize() then finalize.

#define N_PER_CH    262144
#define F4_PER_CH   65536
#define BLKS_PER_CH 16
#define NBLOCKS     (128 * BLKS_PER_CH)        // 2048
#define F4_PER_BLK  (F4_PER_CH / BLKS_PER_CH)  // 4096
#define THREADS     256
#define F4_PER_THR  (F4_PER_BLK / THREADS)     // 16
#define GRP         4
#define NGRP        (F4_PER_THR / GRP)         // 4
#define LS_EPS      1e-4f
#define INV_EPISON  20.0f

static __device__ float4 g_partials[NBLOCKS];   // 32 KB scratch

__device__ __forceinline__ float tanh_fast(float x) {
    float y;
    asm("tanh.approx.f32 %0, %1;" : "=f"(y) : "f"(x));
    return y;
}

__device__ __forceinline__ void accum1(float x, float m,
                                       float& sH, float& sHI, float& sI, float& sI2) {
    float h = fmaf(0.5f, tanh_fast(INV_EPISON * x), 0.5f);
    sH  += h;
    sHI  = fmaf(h, m, sHI);
    sI  += m;
    sI2  = fmaf(m, m, sI2);
}

__global__ void __launch_bounds__(THREADS, 5)
ls_loss_pass1(const float4* __restrict__ inp, const float4* __restrict__ img)
{
    const int b = blockIdx.x;
    const int t = threadIdx.x;
    const long base = (long)b * F4_PER_BLK + t;  // block tiles 1/16 of a channel

    float sH = 0.f, sHI = 0.f, sI = 0.f, sI2 = 0.f;

    #pragma unroll
    for (int g = 0; g < NGRP; g++) {
        float4 x[GRP], m[GRP];
        #pragma unroll
        for (int j = 0; j < GRP; j++) {          // front-batch 8 LDG.128
            const long idx = base + (long)(g * GRP + j) * THREADS;
            x[j] = __ldcs(&inp[idx]);
            m[j] = __ldcs(&img[idx]);
        }
        #pragma unroll
        for (int j = 0; j < GRP; j++) {
            accum1(x[j].x, m[j].x, sH, sHI, sI, sI2);
            accum1(x[j].y, m[j].y, sH, sHI, sI, sI2);
            accum1(x[j].z, m[j].z, sH, sHI, sI, sI2);
            accum1(x[j].w, m[j].w, sH, sHI, sI, sI2);
        }
    }

    // Deterministic warp tree reduce
    #pragma unroll
    for (int o = 16; o > 0; o >>= 1) {
        sH  += __shfl_down_sync(0xFFFFFFFFu, sH,  o);
        sHI += __shfl_down_sync(0xFFFFFFFFu, sHI, o);
        sI  += __shfl_down_sync(0xFFFFFFFFu, sI,  o);
        sI2 += __shfl_down_sync(0xFFFFFFFFu, sI2, o);
    }

    __shared__ float4 sm[THREADS / 32];
    const int warp = t >> 5, lane = t & 31;
    if (lane == 0) sm[warp] = make_float4(sH, sHI, sI, sI2);
    __syncthreads();

    if (t == 0) {
        float4 tot = sm[0];
        #pragma unroll
        for (int w = 1; w < THREADS / 32; w++) {
            float4 v = sm[w];
            tot.x += v.x; tot.y += v.y; tot.z += v.z; tot.w += v.w;
        }
        g_partials[b] = tot;
        __threadfence();                         // publish partial first
        // Fire programmatic completion: pass2 may start ramping once every
        // block has reached this point (i.e., all partials are visible).
        cudaTriggerProgrammaticLaunchCompletion();
    }
}

__global__ void __launch_bounds__(128)
ls_loss_pass2(float* __restrict__ out)
{
    // Wait for pass1's programmatic completion (all partials published).
    cudaGridDependencySynchronize();

    const int c = threadIdx.x;   // one channel per thread

    float A = 0.f, B1 = 0.f, S = 0.f, Q = 0.f;
    #pragma unroll
    for (int i = 0; i < BLKS_PER_CH; i++) {
        float4 v = g_partials[c * BLKS_PER_CH + i];
        A += v.x; B1 += v.y; S += v.z; Q += v.w;
    }

    const float Nf = (float)N_PER_CH;
    const float s3 = Nf - A;
    const float c1 = B1 / (A + LS_EPS);
    const float c2 = (S - B1) / (s3 + LS_EPS);

    float chan = Q - 2.f * (c1 * B1 + c2 * (S - B1))
               + c1 * c1 * A + c2 * c2 * s3;

    #pragma unroll
    for (int o = 16; o > 0; o >>= 1)
        chan += __shfl_down_sync(0xFFFFFFFFu, chan, o);

    __shared__ float sm[4];
    if ((c & 31) == 0) sm[c >> 5] = chan;
    __syncthreads();

    if (c == 0) {
        out[0] = (sm[0] + sm[1] + sm[2] + sm[3])
               / (float)(32 * 4 * N_PER_CH);
    }
}

extern "C" void kernel_launch(void* const* d_in, const int* in_sizes, int n_in,
                              void* d_out, int out_size)
{
    const float4* inp = (const float4*)d_in[0];   // 'input'
    const float4* img = (const float4*)d_in[1];   // 'img_mean'
    float* out = (float*)d_out;

    ls_loss_pass1<<<NBLOCKS, THREADS>>>(inp, img);

    // pass2 via PDL (programmatic serialization); ordered fallback if the
    // Ex-launch path is rejected.
    cudaLaunchConfig_t cfg = {};
    cfg.gridDim  = dim3(1, 1, 1);
    cfg.blockDim = dim3(128, 1, 1);
    cfg.dynamicSmemBytes = 0;
    cfg.stream = 0;
    cudaLaunchAttribute attr[1];
    attr[0].id = cudaLaunchAttributeProgrammaticStreamSerialization;
    attr[0].val.programmaticStreamSerializationAllowed = 1;
    cfg.attrs = attr;
    cfg.numAttrs = 1;
    cudaError_t e = cudaLaunchKernelEx(&cfg, ls_loss_pass2, out);
    if (e != cudaSuccess) {
        (void)cudaGetLastError();
        ls_loss_pass2<<<1, 128>>>(out);
    }
}

// round 12
// speedup vs baseline: 1.0644x; 1.0042x over previous
#include <cuda_runtime.h>

// LS_loss: two-kernel, PDL-triggered epilogue, fine-grained block quantum.
//
// Shapes: input, img_mean : (32, 4, 512, 512) fp32, contiguous.
// 128 channels x 262144 floats (= 65536 float4 each), 32 blocks per channel.
//
// Per channel (N = 262144):
//   Hea = 0.5*(1+tanh(x/0.05))
//   A = sum(Hea), B1 = sum(Hea*img), S = sum(img), Q = sum(img^2)
//   c1 = B1/(A+eps), c2 = (S-B1)/(N-A+eps)
//   chan = Q - 2*(c1*B1 + c2*(S-B1)) + c1^2*A + c2^2*(N-A)
//   out  = sum_chan / (B*C*H*W)
//
// pass1: 4096 blocks x 128 threads (half the prior block quantum -> halves
//        last-wave idle waste); 16 float4-pairs/thread in 4 front-batched
//        groups (MLP~8); fence + programmatic-completion trigger per block.
// pass2: PDL launch; gridDependencySynchronize then finalize (fixed order).

#define N_PER_CH    262144
#define F4_PER_CH   65536
#define BLKS_PER_CH 32
#define NBLOCKS     (128 * BLKS_PER_CH)        // 4096
#define F4_PER_BLK  (F4_PER_CH / BLKS_PER_CH)  // 2048
#define THREADS     128
#define F4_PER_THR  (F4_PER_BLK / THREADS)     // 16
#define GRP         4
#define NGRP        (F4_PER_THR / GRP)         // 4
#define LS_EPS      1e-4f
#define INV_EPISON  20.0f

static __device__ float4 g_partials[NBLOCKS];   // 64 KB scratch

__device__ __forceinline__ float tanh_fast(float x) {
    float y;
    asm("tanh.approx.f32 %0, %1;" : "=f"(y) : "f"(x));
    return y;
}

__device__ __forceinline__ void accum1(float x, float m,
                                       float& sH, float& sHI, float& sI, float& sI2) {
    float h = fmaf(0.5f, tanh_fast(INV_EPISON * x), 0.5f);
    sH  += h;
    sHI  = fmaf(h, m, sHI);
    sI  += m;
    sI2  = fmaf(m, m, sI2);
}

__global__ void __launch_bounds__(THREADS)
ls_loss_pass1(const float4* __restrict__ inp, const float4* __restrict__ img)
{
    const int b = blockIdx.x;
    const int t = threadIdx.x;
    const long base = (long)b * F4_PER_BLK + t;  // block tiles 1/32 of a channel

    float sH = 0.f, sHI = 0.f, sI = 0.f, sI2 = 0.f;

    #pragma unroll
    for (int g = 0; g < NGRP; g++) {
        float4 x[GRP], m[GRP];
        #pragma unroll
        for (int j = 0; j < GRP; j++) {          // front-batch 8 LDG.128
            const long idx = base + (long)(g * GRP + j) * THREADS;
            x[j] = __ldcs(&inp[idx]);
            m[j] = __ldcs(&img[idx]);
        }
        #pragma unroll
        for (int j = 0; j < GRP; j++) {
            accum1(x[j].x, m[j].x, sH, sHI, sI, sI2);
            accum1(x[j].y, m[j].y, sH, sHI, sI, sI2);
            accum1(x[j].z, m[j].z, sH, sHI, sI, sI2);
            accum1(x[j].w, m[j].w, sH, sHI, sI, sI2);
        }
    }

    // Deterministic warp tree reduce
    #pragma unroll
    for (int o = 16; o > 0; o >>= 1) {
        sH  += __shfl_down_sync(0xFFFFFFFFu, sH,  o);
        sHI += __shfl_down_sync(0xFFFFFFFFu, sHI, o);
        sI  += __shfl_down_sync(0xFFFFFFFFu, sI,  o);
        sI2 += __shfl_down_sync(0xFFFFFFFFu, sI2, o);
    }

    __shared__ float4 sm[THREADS / 32];
    const int warp = t >> 5, lane = t & 31;
    if (lane == 0) sm[warp] = make_float4(sH, sHI, sI, sI2);
    __syncthreads();

    if (t == 0) {
        float4 tot = sm[0];
        #pragma unroll
        for (int w = 1; w < THREADS / 32; w++) {
            float4 v = sm[w];
            tot.x += v.x; tot.y += v.y; tot.z += v.z; tot.w += v.w;
        }
        g_partials[b] = tot;
        __threadfence();                         // publish partial first
        // Programmatic completion: dependent pass2 may ramp once all blocks
        // have published their partials.
        cudaTriggerProgrammaticLaunchCompletion();
    }
}

__global__ void __launch_bounds__(128)
ls_loss_pass2(float* __restrict__ out)
{
    cudaGridDependencySynchronize();   // wait for pass1's completion signal

    const int c = threadIdx.x;         // one channel per thread

    float A = 0.f, B1 = 0.f, S = 0.f, Q = 0.f;
    #pragma unroll
    for (int i = 0; i < BLKS_PER_CH; i++) {
        float4 v = g_partials[c * BLKS_PER_CH + i];
        A += v.x; B1 += v.y; S += v.z; Q += v.w;
    }

    const float Nf = (float)N_PER_CH;
    const float s3 = Nf - A;
    const float c1 = B1 / (A + LS_EPS);
    const float c2 = (S - B1) / (s3 + LS_EPS);

    float chan = Q - 2.f * (c1 * B1 + c2 * (S - B1))
               + c1 * c1 * A + c2 * c2 * s3;

    #pragma unroll
    for (int o = 16; o > 0; o >>= 1)
        chan += __shfl_down_sync(0xFFFFFFFFu, chan, o);

    __shared__ float sm[4];
    if ((c & 31) == 0) sm[c >> 5] = chan;
    __syncthreads();

    if (c == 0) {
        out[0] = (sm[0] + sm[1] + sm[2] + sm[3])
               / (float)(32 * 4 * N_PER_CH);
    }
}

extern "C" void kernel_launch(void* const* d_in, const int* in_sizes, int n_in,
                              void* d_out, int out_size)
{
    const float4* inp = (const float4*)d_in[0];   // 'input'
    const float4* img = (const float4*)d_in[1];   // 'img_mean'
    float* out = (float*)d_out;

    ls_loss_pass1<<<NBLOCKS, THREADS>>>(inp, img);

    // pass2 via PDL (programmatic serialization); ordered fallback if the
    // Ex-launch path is rejected.
    cudaLaunchConfig_t cfg = {};
    cfg.gridDim  = dim3(1, 1, 1);
    cfg.blockDim = dim3(128, 1, 1);
    cfg.dynamicSmemBytes = 0;
    cfg.stream = 0;
    cudaLaunchAttribute attr[1];
    attr[0].id = cudaLaunchAttributeProgrammaticStreamSerialization;
    attr[0].val.programmaticStreamSerializationAllowed = 1;
    cfg.attrs = attr;
    cfg.numAttrs = 1;
    cudaError_t e = cudaLaunchKernelEx(&cfg, ls_loss_pass2, out);
    if (e != cudaSuccess) {
        (void)cudaGetLastError();
        ls_loss_pass2<<<1, 128>>>(out);
    }
}